// round 4
// baseline (speedup 1.0000x reference)
#include <cuda_runtime.h>
#include <math.h>

// 4 real circulant coefficients h[d] = Re(ifft(filter)[d]), computed on-device.
__device__ float g_h[4];

// ---------------------------------------------------------------------------
// Kernel A: build the resonant filter from amplitude/phase (24 each), then the
// 4-tap real circular-convolution kernel. Trivial work; single thread.
// ---------------------------------------------------------------------------
__global__ void build_filter_kernel(const float* __restrict__ amp,
                                    const float* __restrict__ phase) {
    if (blockIdx.x != 0 || threadIdx.x != 0) return;

    const float primes[24] = {2.f,3.f,5.f,7.f,11.f,13.f,17.f,19.f,23.f,29.f,
                              31.f,37.f,41.f,43.f,47.f,53.f,59.f,61.f,67.f,
                              71.f,73.f,79.f,83.f,89.f};
    const float PI = 3.14159265358979323846f;

    float fr_re[4], fr_im[4];
    for (int i = 0; i < 4; ++i) {
        float fi = (float)i * 0.25f * PI;
        float re = 0.0f, im = 0.0f;
        for (int k = 0; k < 24; ++k) {
            float pf = primes[k] * (PI / 89.0f);
            float d  = (fi - pf) * 10.0f;            // /0.1
            float g  = expf(-0.5f * d * d);
            float a  = amp[k] * g;
            float s, c;
            sincosf(phase[k], &s, &c);
            re += a * c;
            im += a * s;
        }
        fr_re[i] = re;
        fr_im[i] = im;
    }

    float maxabs = 0.0f;
    for (int i = 0; i < 4; ++i) {
        float m = sqrtf(fr_re[i] * fr_re[i] + fr_im[i] * fr_im[i]);
        if (m > maxabs) maxabs = m;
    }
    float s = 1.0f / (maxabs + 1e-8f);
    for (int i = 0; i < 4; ++i) { fr_re[i] *= s; fr_im[i] *= s; }

    // ifft (N=4) of fr, real part. Twiddles for inverse are powers of +i:
    float r0 = fr_re[0], r1 = fr_re[1], r2 = fr_re[2], r3 = fr_re[3];
    float m1 = fr_im[1], m3 = fr_im[3];
    g_h[0] = 0.25f * (r0 + r1 + r2 + r3);
    g_h[1] = 0.25f * (r0 - m1 - r2 + m3);
    g_h[2] = 0.25f * (r0 - r1 + r2 - r3);
    g_h[3] = 0.25f * (r0 + m1 - r2 - m3);
}

// ---------------------------------------------------------------------------
// Kernel B: streaming circulant 4x4 apply. Two independent float4 per thread
// per iteration for MLP. HBM-bound: 32 B of traffic per 16 FMA.
// ---------------------------------------------------------------------------
__device__ __forceinline__ float4 circ4(float4 v, float h0, float h1,
                                        float h2, float h3) {
    float4 o;
    o.x = h0 * v.x + h3 * v.y + h2 * v.z + h1 * v.w;
    o.y = h1 * v.x + h0 * v.y + h3 * v.z + h2 * v.w;
    o.z = h2 * v.x + h1 * v.y + h0 * v.z + h3 * v.w;
    o.w = h3 * v.x + h2 * v.y + h1 * v.z + h0 * v.w;
    return o;
}

__global__ void apply_filter_kernel(const float4* __restrict__ x,
                                    float4* __restrict__ y,
                                    int n4) {
    const float h0 = g_h[0], h1 = g_h[1], h2 = g_h[2], h3 = g_h[3];
    int stride = gridDim.x * blockDim.x;
    int i = blockIdx.x * blockDim.x + threadIdx.x;

    // Main path: 2 float4 per iteration (front-batched loads -> MLP 2).
    for (; i + stride < n4; i += 2 * stride) {
        float4 a = x[i];
        float4 b = x[i + stride];
        y[i]          = circ4(a, h0, h1, h2, h3);
        y[i + stride] = circ4(b, h0, h1, h2, h3);
    }
    if (i < n4) {
        y[i] = circ4(x[i], h0, h1, h2, h3);
    }
}

extern "C" void kernel_launch(void* const* d_in, const int* in_sizes, int n_in,
                              void* d_out, int out_size) {
    const float* qs    = (const float*)d_in[0];  // [4,2048,1024,4] f32
    const float* amp   = (const float*)d_in[1];  // [24] f32
    const float* phase = (const float*)d_in[2];  // [24] f32
    float* out = (float*)d_out;

    int n  = in_sizes[0];      // total elements (multiple of 4)
    int n4 = n / 4;

    build_filter_kernel<<<1, 32>>>(amp, phase);

    const int threads = 512;
    // Each thread handles 2 float4 -> grid covers n4 in one pass.
    int blocks = (n4 / 2 + threads - 1) / threads;
    if (blocks > 65535) blocks = 65535;
    apply_filter_kernel<<<blocks, threads>>>(
        (const float4*)qs, (float4*)out, n4);
}

// round 6
// speedup vs baseline: 1.1184x; 1.1184x over previous
#include <cuda_runtime.h>
#include <math.h>

__constant__ float c_primes[24] = {2.f,3.f,5.f,7.f,11.f,13.f,17.f,19.f,23.f,29.f,
                                   31.f,37.f,41.f,43.f,47.f,53.f,59.f,61.f,67.f,
                                   71.f,73.f,79.f,83.f,89.f};

__device__ __forceinline__ float4 circ4(float4 v, float h0, float h1,
                                        float h2, float h3) {
    float4 o;
    o.x = h0 * v.x + h3 * v.y + h2 * v.z + h1 * v.w;
    o.y = h1 * v.x + h0 * v.y + h3 * v.z + h2 * v.w;
    o.z = h2 * v.x + h1 * v.y + h0 * v.z + h3 * v.w;
    o.w = h3 * v.x + h2 * v.y + h1 * v.z + h0 * v.w;
    return o;
}

// ---------------------------------------------------------------------------
// Single fused kernel.
// Prologue (per block, parallel): warp w computes freq bin w; lanes 0..23
// produce the Gaussian-bump x phasor terms; shuffle-reduce; thread 0
// normalizes by max-|fr| and applies the 4-point IFFT -> 4 real circulant
// taps in shared memory.
// Body: grid-stride streaming circulant 4x4 apply, 4 float4 in flight.
// ---------------------------------------------------------------------------
__global__ void prime_resonant_fused(const float4* __restrict__ x,
                                     float4* __restrict__ y,
                                     const float* __restrict__ amp,
                                     const float* __restrict__ phase,
                                     int n4) {
    __shared__ float sh_h[4];
    __shared__ float s_re[4], s_im[4];

    const int tid  = threadIdx.x;
    const int warp = tid >> 5;
    const int lane = tid & 31;
    const float PI = 3.14159265358979323846f;

    if (warp < 4) {
        float re = 0.0f, im = 0.0f;
        if (lane < 24) {
            float pf = c_primes[lane] * (PI / 89.0f);
            float fi = (float)warp * 0.25f * PI;
            float d  = (fi - pf) * 10.0f;            // sigma = 0.1
            float g  = expf(-0.5f * d * d);
            float a  = amp[lane] * g;
            float s, c;
            sincosf(phase[lane], &s, &c);
            re = a * c;
            im = a * s;
        }
        #pragma unroll
        for (int o = 16; o; o >>= 1) {
            re += __shfl_down_sync(0xffffffffu, re, o);
            im += __shfl_down_sync(0xffffffffu, im, o);
        }
        if (lane == 0) { s_re[warp] = re; s_im[warp] = im; }
    }
    __syncthreads();

    if (tid == 0) {
        float maxabs = 0.0f;
        #pragma unroll
        for (int i = 0; i < 4; ++i) {
            float m = sqrtf(s_re[i] * s_re[i] + s_im[i] * s_im[i]);
            if (m > maxabs) maxabs = m;
        }
        float s = 1.0f / (maxabs + 1e-8f);
        float r0 = s_re[0] * s, r1 = s_re[1] * s, r2 = s_re[2] * s, r3 = s_re[3] * s;
        float m1 = s_im[1] * s, m3 = s_im[3] * s;
        // Real part of ifft_4(filter): twiddles are powers of +i.
        sh_h[0] = 0.25f * (r0 + r1 + r2 + r3);
        sh_h[1] = 0.25f * (r0 - m1 - r2 + m3);
        sh_h[2] = 0.25f * (r0 - r1 + r2 - r3);
        sh_h[3] = 0.25f * (r0 + m1 - r2 - m3);
    }
    __syncthreads();

    const float h0 = sh_h[0], h1 = sh_h[1], h2 = sh_h[2], h3 = sh_h[3];

    const int S = gridDim.x * blockDim.x;
    int i = blockIdx.x * blockDim.x + tid;

    // 4 independent float4 in flight per iteration (MLP 4), streaming hints.
    for (; i + 3 * S < n4; i += 4 * S) {
        float4 a = __ldcs(&x[i]);
        float4 b = __ldcs(&x[i + S]);
        float4 c = __ldcs(&x[i + 2 * S]);
        float4 d = __ldcs(&x[i + 3 * S]);
        __stcs(&y[i],         circ4(a, h0, h1, h2, h3));
        __stcs(&y[i + S],     circ4(b, h0, h1, h2, h3));
        __stcs(&y[i + 2 * S], circ4(c, h0, h1, h2, h3));
        __stcs(&y[i + 3 * S], circ4(d, h0, h1, h2, h3));
    }
    for (; i < n4; i += S) {
        __stcs(&y[i], circ4(__ldcs(&x[i]), h0, h1, h2, h3));
    }
}

extern "C" void kernel_launch(void* const* d_in, const int* in_sizes, int n_in,
                              void* d_out, int out_size) {
    const float* qs    = (const float*)d_in[0];  // [4,2048,1024,4] f32
    const float* amp   = (const float*)d_in[1];  // [24] f32
    const float* phase = (const float*)d_in[2];  // [24] f32
    float* out = (float*)d_out;

    int n  = in_sizes[0];
    int n4 = n / 4;

    const int threads = 512;
    const int blocks  = 1184;   // 8 CTAs/SM nominal; grid-stride covers n4
    prime_resonant_fused<<<blocks, threads>>>(
        (const float4*)qs, (float4*)out, amp, phase, n4);
}